// round 6
// baseline (speedup 1.0000x reference)
#include <cuda_runtime.h>
#include <cuda_fp16.h>

#define NU 200000
#define NI 100000
#define NT 300000          // NU + NI
#define NE 4000000
#define NB ((NT + 1023) / 1024)   // scan blocks = 293

// -------- device scratch (no allocations allowed) --------
__device__ __half2 g_a[NT * 32];   // y0
__device__ __half2 g_b[NT * 32];   // y1
__device__ __half2 g_c[NT * 32];   // y2
__device__ int   g_deg[NT];
__device__ float g_dinv[NT];
__device__ int   g_rowptr[NT + 1]; // after scatter: rowptr[i] = end of row i
__device__ int   g_agg[NB];        // per-block aggregates for single-pass scan
__device__ volatile int g_flag[NB];
__device__ int   g_col[NE];        // dst, CSR-ordered by src

__device__ __forceinline__ __half2* buf(int s) {
    return (s == 0) ? g_a : (s == 1) ? g_b : g_c;
}

// -------- 1: zero deg + scan flags --------
__global__ void k_zero() {
    int i = blockIdx.x * blockDim.x + threadIdx.x;
    if (i < NT) g_deg[i] = 0;
    if (i < NB) g_flag[i] = 0;
    if (i == 0) g_rowptr[NT] = NE;
}

// -------- 2: degree histogram --------
__global__ void k_hist(const int4* __restrict__ src4) {
    int i = blockIdx.x * blockDim.x + threadIdx.x;
    if (i < NE / 4) {
        int4 s = src4[i];
        atomicAdd(&g_deg[s.x], 1);
        atomicAdd(&g_deg[s.y], 1);
        atomicAdd(&g_deg[s.z], 1);
        atomicAdd(&g_deg[s.w], 1);
    }
}

// -------- 3: single-pass scan (deg -> rowptr), dinv fused --------
// Each block publishes its aggregate; blocks sum all predecessor aggregates
// (aggregates never depend on other blocks -> no deadlock).
__global__ void __launch_bounds__(1024) k_scan() {
    __shared__ int ws[32];
    __shared__ int s_prev;
    int b = blockIdx.x;
    int i = b * 1024 + threadIdx.x;
    int v = (i < NT) ? g_deg[i] : 0;
    if (i < NT) g_dinv[i] = rsqrtf((float)v + 1e-8f);
    int lane = threadIdx.x & 31, wid = threadIdx.x >> 5;

    // block-local inclusive scan
    int x = v;
    #pragma unroll
    for (int o = 1; o < 32; o <<= 1) {
        int y = __shfl_up_sync(0xffffffffu, x, o);
        if (lane >= o) x += y;
    }
    if (lane == 31) ws[wid] = x;
    __syncthreads();
    if (wid == 0) {
        int s = ws[lane];
        #pragma unroll
        for (int o = 1; o < 32; o <<= 1) {
            int y = __shfl_up_sync(0xffffffffu, s, o);
            if (lane >= o) s += y;
        }
        ws[lane] = s;
    }
    __syncthreads();
    int excl = x - v + (wid > 0 ? ws[wid - 1] : 0);
    int btotal = ws[31];

    // publish aggregate
    if (threadIdx.x == 0) {
        g_agg[b] = btotal;
        __threadfence();
        g_flag[b] = 1;
    }

    // gather predecessor aggregates (thread t handles block t, t < b <= 292)
    int myagg = 0;
    if ((int)threadIdx.x < b) {
        while (g_flag[threadIdx.x] == 0) { }
        myagg = g_agg[threadIdx.x];
    }
    // block reduce myagg
    #pragma unroll
    for (int o = 16; o > 0; o >>= 1)
        myagg += __shfl_down_sync(0xffffffffu, myagg, o);
    __syncthreads();               // ws reuse barrier
    if (lane == 0) ws[wid] = myagg;
    __syncthreads();
    if (threadIdx.x == 0) {
        int t = 0;
        #pragma unroll
        for (int w = 0; w < 32; w++) t += ws[w];
        s_prev = t;
    }
    __syncthreads();

    if (i < NT) g_rowptr[i] = excl + s_prev;
}

// -------- 4: init y0 = dinv * x (fp16) --------
__global__ void k_init(const float2* __restrict__ uw, const float2* __restrict__ iw) {
    int i = blockIdx.x * blockDim.x + threadIdx.x;   // half2 element index
    const int NU2 = NU * 32;
    const int NT2 = NT * 32;
    if (i < NT2) {
        float2 v = (i < NU2) ? uw[i] : iw[i - NU2];
        float di = g_dinv[i >> 5];
        g_a[i] = __floats2half2_rn(di * v.x, di * v.y);
    }
}

// -------- 5: scatter edges; atomic cursor IS rowptr (ends at row end) --------
__global__ void k_scatter(const int* __restrict__ src, const int* __restrict__ dst) {
    int e = blockIdx.x * blockDim.x + threadIdx.x;
    if (e < NE) {
        int p = atomicAdd(&g_rowptr[src[e]], 1);
        g_col[p] = dst[e];
    }
}

// -------- 6-8: SpMM, warp per row; beg = rowptr[gw]-deg[gw], end = rowptr[gw] --------
// LAST=0: store dinv^2*s (propagated y). LAST=1: fused epilogue writes out.
template<int S, int DBUF, int LAST>
__global__ void __launch_bounds__(256) k_spmm(const float2* __restrict__ uw,
                                              const float2* __restrict__ iw,
                                              float2* __restrict__ out) {
    int gw = (blockIdx.x * 256 + threadIdx.x) >> 5;
    if (gw >= NT) return;
    int lane = threadIdx.x & 31;

    const __half2* __restrict__ y = buf(S);

    int end = g_rowptr[gw];
    int beg = end - g_deg[gw];

    float sx0 = 0.f, sy0 = 0.f, sx1 = 0.f, sy1 = 0.f;
    for (int base = beg; base < end; base += 32) {
        int n = end - base; if (n > 32) n = 32;
        int myc = (base + lane < end) ? g_col[base + lane] : 0;
        int k = 0;
        for (; k + 4 <= n; k += 4) {
            int c0 = __shfl_sync(0xffffffffu, myc, k + 0);
            int c1 = __shfl_sync(0xffffffffu, myc, k + 1);
            int c2 = __shfl_sync(0xffffffffu, myc, k + 2);
            int c3 = __shfl_sync(0xffffffffu, myc, k + 3);
            float2 v0 = __half22float2(y[c0 * 32 + lane]);
            float2 v1 = __half22float2(y[c1 * 32 + lane]);
            float2 v2 = __half22float2(y[c2 * 32 + lane]);
            float2 v3 = __half22float2(y[c3 * 32 + lane]);
            sx0 += v0.x; sy0 += v0.y;
            sx1 += v1.x; sy1 += v1.y;
            sx0 += v2.x; sy0 += v2.y;
            sx1 += v3.x; sy1 += v3.y;
        }
        for (; k < n; k++) {
            int c = __shfl_sync(0xffffffffu, myc, k);
            float2 v = __half22float2(y[c * 32 + lane]);
            sx0 += v.x; sy0 += v.y;
        }
    }
    float s_x = sx0 + sx1, s_y = sy0 + sy1;

    float di = g_dinv[gw];
    int o = gw * 32 + lane;
    if (!LAST) {
        __half2* __restrict__ w = buf(DBUF);
        float f = di * di;
        w[o] = __floats2half2_rn(f * s_x, f * s_y);
    } else {
        // h3 = di*s; out = 0.25*(x + inv*(y1+y2) + h3)
        float hx = di * s_x, hy = di * s_y;
        float inv = __frcp_rn(di);                 // = sqrt(deg + 1e-8)
        float2 v  = (gw < NU) ? uw[o] : iw[o - NU * 32];
        float2 y1 = __half22float2(g_b[o]);
        float2 y2 = __half22float2(g_c[o]);
        out[o] = make_float2(0.25f * (v.x + inv * (y1.x + y2.x) + hx),
                             0.25f * (v.y + inv * (y1.y + y2.y) + hy));
    }
}

extern "C" void kernel_launch(void* const* d_in, const int* in_sizes, int n_in,
                              void* d_out, int out_size) {
    const float* uw  = (const float*)d_in[0];
    const float* iw  = (const float*)d_in[1];
    const int*   src = (const int*)d_in[2];
    const int*   dst = (const int*)d_in[3];
    float* out = (float*)d_out;

    // launches: zero(1) hist(2) scan(3) init(4) scatter(5) spmm1(6) spmm2(7) spmm3(8)
    k_zero<<<(NT + 255) / 256, 256>>>();
    k_hist<<<(NE / 4 + 255) / 256, 256>>>((const int4*)src);
    k_scan<<<NB, 1024>>>();
    k_init<<<(NT * 32 + 255) / 256, 256>>>((const float2*)uw, (const float2*)iw);
    k_scatter<<<(NE + 255) / 256, 256>>>(src, dst);

    int nblk = (NT * 32 + 255) / 256;
    k_spmm<0, 1, 0><<<nblk, 256>>>((const float2*)uw, (const float2*)iw, (float2*)out);
    k_spmm<1, 2, 0><<<nblk, 256>>>((const float2*)uw, (const float2*)iw, (float2*)out);
    k_spmm<2, 0, 1><<<nblk, 256>>>((const float2*)uw, (const float2*)iw, (float2*)out);
}

// round 7
// speedup vs baseline: 1.3849x; 1.3849x over previous
#include <cuda_runtime.h>
#include <cuda_fp16.h>

#define NU 200000
#define NI 100000
#define NT 300000          // NU + NI
#define NE 4000000
#define NB ((NT + 1023) / 1024)   // scan blocks = 293

// -------- device scratch (no allocations allowed) --------
__device__ __half2 g_a[NT * 32];   // y0
__device__ __half2 g_b[NT * 32];   // y1
__device__ __half2 g_c[NT * 32];   // y2
__device__ int   g_deg[NT];
__device__ int   g_pos[NT];
__device__ float g_dinv[NT];
__device__ int   g_rowptr[NT + 1];
__device__ int   g_bsum[NB];
__device__ int   g_col[NE];        // dst, CSR-ordered by src

__device__ __forceinline__ __half2* buf(int s) {
    return (s == 0) ? g_a : (s == 1) ? g_b : g_c;
}

// -------- build: degree histogram --------
__global__ void k_hist(const int4* __restrict__ src4) {
    int i = blockIdx.x * blockDim.x + threadIdx.x;
    if (i < NE / 4) {
        int4 s = src4[i];
        atomicAdd(&g_deg[s.x], 1);
        atomicAdd(&g_deg[s.y], 1);
        atomicAdd(&g_deg[s.z], 1);
        atomicAdd(&g_deg[s.w], 1);
    }
}

// -------- build: scan phase A (dinv fused) --------
__global__ void k_scanA() {
    __shared__ int ws[32];
    int i = blockIdx.x * 1024 + threadIdx.x;
    int v = (i < NT) ? g_deg[i] : 0;
    if (i < NT) g_dinv[i] = rsqrtf((float)v + 1e-8f);
    int lane = threadIdx.x & 31, wid = threadIdx.x >> 5;
    int x = v;
    #pragma unroll
    for (int o = 1; o < 32; o <<= 1) {
        int y = __shfl_up_sync(0xffffffffu, x, o);
        if (lane >= o) x += y;
    }
    if (lane == 31) ws[wid] = x;
    __syncthreads();
    if (wid == 0) {
        int s = ws[lane];
        #pragma unroll
        for (int o = 1; o < 32; o <<= 1) {
            int y = __shfl_up_sync(0xffffffffu, s, o);
            if (lane >= o) s += y;
        }
        ws[lane] = s;
    }
    __syncthreads();
    int excl = x - v + (wid > 0 ? ws[wid - 1] : 0);
    if (i < NT) g_rowptr[i] = excl;
    if (threadIdx.x == 1023) g_bsum[blockIdx.x] = ws[31];
}

// -------- build: scan phase B --------
__global__ void k_scanB() {
    __shared__ int ws[16];
    int t = threadIdx.x;
    int v = (t < NB) ? g_bsum[t] : 0;
    int lane = t & 31, wid = t >> 5;
    int x = v;
    #pragma unroll
    for (int o = 1; o < 32; o <<= 1) {
        int y = __shfl_up_sync(0xffffffffu, x, o);
        if (lane >= o) x += y;
    }
    if (lane == 31) ws[wid] = x;
    __syncthreads();
    if (wid == 0) {
        int s = (lane < 16) ? ws[lane] : 0;
        #pragma unroll
        for (int o = 1; o < 32; o <<= 1) {
            int y = __shfl_up_sync(0xffffffffu, s, o);
            if (lane >= o) s += y;
        }
        if (lane < 16) ws[lane] = s;
    }
    __syncthreads();
    int excl = x - v + (wid > 0 ? ws[wid - 1] : 0);
    if (t < NB) g_bsum[t] = excl;
    if (t == 0) g_rowptr[NT] = ws[15];   // = NE
}

// -------- fused: scanC (rowptr fix-up) + init (y0 = dinv*x fp16) --------
__global__ void k_fixinit(const float2* __restrict__ uw, const float2* __restrict__ iw) {
    int i = blockIdx.x * blockDim.x + threadIdx.x;   // half2 element index
    const int NU2 = NU * 32;
    const int NT2 = NT * 32;
    if (i < NT) g_rowptr[i] += g_bsum[i >> 10];
    if (i < NT2) {
        float2 v = (i < NU2) ? uw[i] : iw[i - NU2];
        float di = g_dinv[i >> 5];
        g_a[i] = __floats2half2_rn(di * v.x, di * v.y);
    }
}

// -------- build: scatter edges into CSR (atomic cursor; spread addrs = cheap) --------
__global__ void k_scatter(const int* __restrict__ src, const int* __restrict__ dst) {
    int e = blockIdx.x * blockDim.x + threadIdx.x;
    if (e < NE) {
        int s = src[e];
        int p = atomicAdd(&g_pos[s], 1);
        g_col[g_rowptr[s] + p] = dst[e];
    }
}

// -------- SpMM: 2 rows per warp; 16 lanes per row, lane owns 4 dims (uint2) --------
// LAST=0: store dinv^2*s (propagated y). LAST=1: fused epilogue writes out.
template<int S, int DBUF, int LAST>
__global__ void __launch_bounds__(256) k_spmm(const float4* __restrict__ uw,
                                              const float4* __restrict__ iw,
                                              float4* __restrict__ out) {
    int w = (blockIdx.x * 256 + threadIdx.x) >> 5;   // warp id: 0 .. NT/2-1
    if (w >= NT / 2) return;
    int lane   = threadIdx.x & 31;
    int lane16 = lane & 15;
    int half   = lane >> 4;
    int r = w * 2 + half;                            // this half-warp's row

    const uint2* __restrict__ y = (const uint2*)buf(S);

    int beg = g_rowptr[r];
    int n   = g_rowptr[r + 1] - beg;
    int nOther = __shfl_xor_sync(0xffffffffu, n, 16);
    int nMax = n > nOther ? n : nOther;

    float ax = 0.f, ay = 0.f, az = 0.f, aw = 0.f;
    for (int base = 0; base < nMax; base += 16) {
        int e = base + lane16;
        int myc = (e < n) ? g_col[beg + e] : -1;
        #pragma unroll
        for (int k = 0; k < 16; k++) {
            int c = __shfl_sync(0xffffffffu, myc, k, 16);  // within 16-lane segment
            if (c >= 0) {
                uint2 raw = y[c * 16 + lane16];
                float2 f0 = __half22float2(*(const __half2*)&raw.x);
                float2 f1 = __half22float2(*(const __half2*)&raw.y);
                ax += f0.x; ay += f0.y; az += f1.x; aw += f1.y;
            }
        }
    }

    float di = g_dinv[r];
    int o = r * 16 + lane16;
    if (!LAST) {
        float f = di * di;
        __half2 h0 = __floats2half2_rn(f * ax, f * ay);
        __half2 h1 = __floats2half2_rn(f * az, f * aw);
        uint2 raw;
        raw.x = *(const unsigned*)&h0;
        raw.y = *(const unsigned*)&h1;
        ((uint2*)buf(DBUF))[o] = raw;
    } else {
        // h3 = di*s; out = 0.25*(x + inv*(y1+y2) + h3)
        float inv = __frcp_rn(di);                   // = sqrt(deg + 1e-8)
        float4 v  = (r < NU) ? uw[o] : iw[o - NU * 16];
        uint2 rb = ((const uint2*)g_b)[o];
        uint2 rc = ((const uint2*)g_c)[o];
        float2 b0 = __half22float2(*(const __half2*)&rb.x);
        float2 b1 = __half22float2(*(const __half2*)&rb.y);
        float2 c0 = __half22float2(*(const __half2*)&rc.x);
        float2 c1 = __half22float2(*(const __half2*)&rc.y);
        out[o] = make_float4(
            0.25f * (v.x + inv * (b0.x + c0.x) + di * ax),
            0.25f * (v.y + inv * (b0.y + c0.y) + di * ay),
            0.25f * (v.z + inv * (b1.x + c1.x) + di * az),
            0.25f * (v.w + inv * (b1.y + c1.y) + di * aw));
    }
}

extern "C" void kernel_launch(void* const* d_in, const int* in_sizes, int n_in,
                              void* d_out, int out_size) {
    const float* uw  = (const float*)d_in[0];
    const float* iw  = (const float*)d_in[1];
    const int*   src = (const int*)d_in[2];
    const int*   dst = (const int*)d_in[3];
    float* out = (float*)d_out;

    // zero deg + pos via memset nodes
    void *p_deg = nullptr, *p_pos = nullptr;
    cudaGetSymbolAddress(&p_deg, g_deg);
    cudaGetSymbolAddress(&p_pos, g_pos);
    cudaMemsetAsync(p_deg, 0, NT * sizeof(int));
    cudaMemsetAsync(p_pos, 0, NT * sizeof(int));

    // CSR build + init
    k_hist<<<(NE / 4 + 255) / 256, 256>>>((const int4*)src);
    k_scanA<<<NB, 1024>>>();
    k_scanB<<<1, 512>>>();
    k_fixinit<<<(NT * 32 + 255) / 256, 256>>>((const float2*)uw, (const float2*)iw);
    k_scatter<<<(NE + 255) / 256, 256>>>(src, dst);

    // 3 propagation layers; 2 rows per warp
    int nblk = (NT / 2 * 32 + 255) / 256;
    k_spmm<0, 1, 0><<<nblk, 256>>>((const float4*)uw, (const float4*)iw, (float4*)out);
    k_spmm<1, 2, 0><<<nblk, 256>>>((const float4*)uw, (const float4*)iw, (float4*)out);
    k_spmm<2, 0, 1><<<nblk, 256>>>((const float4*)uw, (const float4*)iw, (float4*)out);
}

// round 8
// speedup vs baseline: 1.4729x; 1.0635x over previous
#include <cuda_runtime.h>
#include <cuda_fp16.h>

#define NU 200000
#define NI 100000
#define NT 300000          // NU + NI
#define NE 4000000
#define NB ((NT + 1023) / 1024)   // scan blocks = 293

// -------- device scratch (no allocations allowed) --------
__device__ __half2 g_a[NT * 32];   // y0
__device__ __half2 g_b[NT * 32];   // y1
__device__ __half2 g_c[NT * 32];   // y2
__device__ int   g_deg[NT];
__device__ int   g_pos[NT];
__device__ float g_dinv[NT];
__device__ int   g_rowptr[NT + 1];
__device__ int   g_bsum[NB];
__device__ int   g_col[NE];        // dst, CSR-ordered by src

__device__ __forceinline__ __half2* buf(int s) {
    return (s == 0) ? g_a : (s == 1) ? g_b : g_c;
}

// -------- build: degree histogram --------
__global__ void k_hist(const int4* __restrict__ src4) {
    int i = blockIdx.x * blockDim.x + threadIdx.x;
    if (i < NE / 4) {
        int4 s = src4[i];
        atomicAdd(&g_deg[s.x], 1);
        atomicAdd(&g_deg[s.y], 1);
        atomicAdd(&g_deg[s.z], 1);
        atomicAdd(&g_deg[s.w], 1);
    }
}

// -------- build: scan phase A (dinv fused) --------
__global__ void k_scanA() {
    __shared__ int ws[32];
    int i = blockIdx.x * 1024 + threadIdx.x;
    int v = (i < NT) ? g_deg[i] : 0;
    if (i < NT) g_dinv[i] = rsqrtf((float)v + 1e-8f);
    int lane = threadIdx.x & 31, wid = threadIdx.x >> 5;
    int x = v;
    #pragma unroll
    for (int o = 1; o < 32; o <<= 1) {
        int y = __shfl_up_sync(0xffffffffu, x, o);
        if (lane >= o) x += y;
    }
    if (lane == 31) ws[wid] = x;
    __syncthreads();
    if (wid == 0) {
        int s = ws[lane];
        #pragma unroll
        for (int o = 1; o < 32; o <<= 1) {
            int y = __shfl_up_sync(0xffffffffu, s, o);
            if (lane >= o) s += y;
        }
        ws[lane] = s;
    }
    __syncthreads();
    int excl = x - v + (wid > 0 ? ws[wid - 1] : 0);
    if (i < NT) g_rowptr[i] = excl;
    if (threadIdx.x == 1023) g_bsum[blockIdx.x] = ws[31];
}

// -------- build: scan phase B --------
__global__ void k_scanB() {
    __shared__ int ws[16];
    int t = threadIdx.x;
    int v = (t < NB) ? g_bsum[t] : 0;
    int lane = t & 31, wid = t >> 5;
    int x = v;
    #pragma unroll
    for (int o = 1; o < 32; o <<= 1) {
        int y = __shfl_up_sync(0xffffffffu, x, o);
        if (lane >= o) x += y;
    }
    if (lane == 31) ws[wid] = x;
    __syncthreads();
    if (wid == 0) {
        int s = (lane < 16) ? ws[lane] : 0;
        #pragma unroll
        for (int o = 1; o < 32; o <<= 1) {
            int y = __shfl_up_sync(0xffffffffu, s, o);
            if (lane >= o) s += y;
        }
        if (lane < 16) ws[lane] = s;
    }
    __syncthreads();
    int excl = x - v + (wid > 0 ? ws[wid - 1] : 0);
    if (t < NB) g_bsum[t] = excl;
    if (t == 0) g_rowptr[NT] = ws[15];   // = NE
}

// -------- fused: scanC (rowptr fix-up) + init (y0 = dinv*x fp16) --------
__global__ void k_fixinit(const float2* __restrict__ uw, const float2* __restrict__ iw) {
    int i = blockIdx.x * blockDim.x + threadIdx.x;   // half2 element index
    const int NU2 = NU * 32;
    const int NT2 = NT * 32;
    if (i < NT) g_rowptr[i] += g_bsum[i >> 10];
    if (i < NT2) {
        float2 v = (i < NU2) ? uw[i] : iw[i - NU2];
        float di = g_dinv[i >> 5];
        g_a[i] = __floats2half2_rn(di * v.x, di * v.y);
    }
}

// -------- build: scatter edges into CSR (atomic cursor; spread addrs = cheap) --------
__global__ void k_scatter(const int* __restrict__ src, const int* __restrict__ dst) {
    int e = blockIdx.x * blockDim.x + threadIdx.x;
    if (e < NE) {
        int s = src[e];
        int p = atomicAdd(&g_pos[s], 1);
        g_col[g_rowptr[s] + p] = dst[e];
    }
}

// -------- SpMM: 4 rows per warp; 8 lanes per row, lane owns 8 dims (uint4) --------
// LAST=0: store dinv^2*s (propagated y). LAST=1: fused epilogue writes out.
template<int S, int DBUF, int LAST>
__global__ void __launch_bounds__(256) k_spmm(const float4* __restrict__ uw,
                                              const float4* __restrict__ iw,
                                              float4* __restrict__ out) {
    int w = (blockIdx.x * 256 + threadIdx.x) >> 5;   // warp id: 0 .. NT/4-1
    if (w >= NT / 4) return;
    int lane  = threadIdx.x & 31;
    int lane8 = lane & 7;
    int seg   = lane >> 3;                           // 0..3
    int r = w * 4 + seg;                             // this segment's row

    const uint4* __restrict__ y = (const uint4*)buf(S);

    int beg = g_rowptr[r];
    int n   = g_rowptr[r + 1] - beg;
    // warp-wide max degree over the 4 segments
    int nMax = n;
    nMax = max(nMax, __shfl_xor_sync(0xffffffffu, nMax, 8));
    nMax = max(nMax, __shfl_xor_sync(0xffffffffu, nMax, 16));

    float a0 = 0.f, a1 = 0.f, a2 = 0.f, a3 = 0.f;
    float a4 = 0.f, a5 = 0.f, a6 = 0.f, a7 = 0.f;
    for (int base = 0; base < nMax; base += 8) {
        int e = base + lane8;
        int myc = (e < n) ? g_col[beg + e] : -1;
        #pragma unroll
        for (int k = 0; k < 8; k++) {
            int c = __shfl_sync(0xffffffffu, myc, k, 8);   // within 8-lane segment
            if (c >= 0) {
                uint4 raw = y[c * 8 + lane8];
                float2 f0 = __half22float2(*(const __half2*)&raw.x);
                float2 f1 = __half22float2(*(const __half2*)&raw.y);
                float2 f2 = __half22float2(*(const __half2*)&raw.z);
                float2 f3 = __half22float2(*(const __half2*)&raw.w);
                a0 += f0.x; a1 += f0.y; a2 += f1.x; a3 += f1.y;
                a4 += f2.x; a5 += f2.y; a6 += f3.x; a7 += f3.y;
            }
        }
    }

    float di = g_dinv[r];
    int o = r * 8 + lane8;                           // uint4 index within y-layout
    if (!LAST) {
        float f = di * di;
        __half2 h0 = __floats2half2_rn(f * a0, f * a1);
        __half2 h1 = __floats2half2_rn(f * a2, f * a3);
        __half2 h2 = __floats2half2_rn(f * a4, f * a5);
        __half2 h3 = __floats2half2_rn(f * a6, f * a7);
        uint4 raw;
        raw.x = *(const unsigned*)&h0;
        raw.y = *(const unsigned*)&h1;
        raw.z = *(const unsigned*)&h2;
        raw.w = *(const unsigned*)&h3;
        ((uint4*)buf(DBUF))[o] = raw;
    } else {
        // h = di*s; out = 0.25*(x + inv*(y1+y2) + h)
        float inv = __frcp_rn(di);                   // = sqrt(deg + 1e-8)
        uint4 rb = ((const uint4*)g_b)[o];
        uint4 rc = ((const uint4*)g_c)[o];
        float2 b0 = __half22float2(*(const __half2*)&rb.x);
        float2 b1 = __half22float2(*(const __half2*)&rb.y);
        float2 b2 = __half22float2(*(const __half2*)&rb.z);
        float2 b3 = __half22float2(*(const __half2*)&rb.w);
        float2 c0 = __half22float2(*(const __half2*)&rc.x);
        float2 c1 = __half22float2(*(const __half2*)&rc.y);
        float2 c2 = __half22float2(*(const __half2*)&rc.z);
        float2 c3 = __half22float2(*(const __half2*)&rc.w);
        int fo = r * 16 + lane8 * 2;                 // float4 index (row = 16 float4)
        const float4* xsrc = (r < NU) ? uw + fo : iw + (fo - NU * 16);
        float4 v0 = xsrc[0];
        float4 v1 = xsrc[1];
        out[fo] = make_float4(
            0.25f * (v0.x + inv * (b0.x + c0.x) + di * a0),
            0.25f * (v0.y + inv * (b0.y + c0.y) + di * a1),
            0.25f * (v0.z + inv * (b1.x + c1.x) + di * a2),
            0.25f * (v0.w + inv * (b1.y + c1.y) + di * a3));
        out[fo + 1] = make_float4(
            0.25f * (v1.x + inv * (b2.x + c2.x) + di * a4),
            0.25f * (v1.y + inv * (b2.y + c2.y) + di * a5),
            0.25f * (v1.z + inv * (b3.x + c3.x) + di * a6),
            0.25f * (v1.w + inv * (b3.y + c3.y) + di * a7));
    }
}

extern "C" void kernel_launch(void* const* d_in, const int* in_sizes, int n_in,
                              void* d_out, int out_size) {
    const float* uw  = (const float*)d_in[0];
    const float* iw  = (const float*)d_in[1];
    const int*   src = (const int*)d_in[2];
    const int*   dst = (const int*)d_in[3];
    float* out = (float*)d_out;

    // zero deg + pos via memset nodes
    void *p_deg = nullptr, *p_pos = nullptr;
    cudaGetSymbolAddress(&p_deg, g_deg);
    cudaGetSymbolAddress(&p_pos, g_pos);
    cudaMemsetAsync(p_deg, 0, NT * sizeof(int));
    cudaMemsetAsync(p_pos, 0, NT * sizeof(int));

    // CSR build + init
    k_hist<<<(NE / 4 + 255) / 256, 256>>>((const int4*)src);
    k_scanA<<<NB, 1024>>>();
    k_scanB<<<1, 512>>>();
    k_fixinit<<<(NT * 32 + 255) / 256, 256>>>((const float2*)uw, (const float2*)iw);
    k_scatter<<<(NE + 255) / 256, 256>>>(src, dst);

    // 3 propagation layers; 4 rows per warp
    int nblk = (NT / 4 * 32 + 255) / 256;
    k_spmm<0, 1, 0><<<nblk, 256>>>((const float4*)uw, (const float4*)iw, (float4*)out);
    k_spmm<1, 2, 0><<<nblk, 256>>>((const float4*)uw, (const float4*)iw, (float4*)out);
    k_spmm<2, 0, 1><<<nblk, 256>>>((const float4*)uw, (const float4*)iw, (float4*)out);
}

// round 9
// speedup vs baseline: 1.5675x; 1.0642x over previous
#include <cuda_runtime.h>
#include <cuda_fp16.h>

#define NU 200000
#define NI 100000
#define NT 300000          // NU + NI
#define NE 4000000
#define NB ((NT + 1023) / 1024)   // scan blocks = 293

// -------- device scratch (no allocations allowed) --------
__device__ __half2 g_a[NT * 32];   // y0 (kept alive through layer 3 for x reconstruction)
__device__ __half2 g_b[NT * 32];   // y1
__device__ __half2 g_c[NT * 32];   // y2
__device__ int   g_deg[NT];
__device__ int   g_pos[NT];
__device__ float g_dinv[NT];
__device__ int   g_rowptr[NT + 1];
__device__ int   g_bsum[NB];
__device__ int   g_col[NE];        // dst, CSR-ordered by src

__device__ __forceinline__ __half2* buf(int s) {
    return (s == 0) ? g_a : (s == 1) ? g_b : g_c;
}

// -------- build: degree histogram --------
__global__ void k_hist(const int4* __restrict__ src4) {
    int i = blockIdx.x * blockDim.x + threadIdx.x;
    if (i < NE / 4) {
        int4 s = src4[i];
        atomicAdd(&g_deg[s.x], 1);
        atomicAdd(&g_deg[s.y], 1);
        atomicAdd(&g_deg[s.z], 1);
        atomicAdd(&g_deg[s.w], 1);
    }
}

// -------- build: scan phase A (dinv fused) --------
__global__ void k_scanA() {
    __shared__ int ws[32];
    int i = blockIdx.x * 1024 + threadIdx.x;
    int v = (i < NT) ? g_deg[i] : 0;
    if (i < NT) g_dinv[i] = rsqrtf((float)v + 1e-8f);
    int lane = threadIdx.x & 31, wid = threadIdx.x >> 5;
    int x = v;
    #pragma unroll
    for (int o = 1; o < 32; o <<= 1) {
        int y = __shfl_up_sync(0xffffffffu, x, o);
        if (lane >= o) x += y;
    }
    if (lane == 31) ws[wid] = x;
    __syncthreads();
    if (wid == 0) {
        int s = ws[lane];
        #pragma unroll
        for (int o = 1; o < 32; o <<= 1) {
            int y = __shfl_up_sync(0xffffffffu, s, o);
            if (lane >= o) s += y;
        }
        ws[lane] = s;
    }
    __syncthreads();
    int excl = x - v + (wid > 0 ? ws[wid - 1] : 0);
    if (i < NT) g_rowptr[i] = excl;
    if (threadIdx.x == 1023) g_bsum[blockIdx.x] = ws[31];
}

// -------- build: scan phase B --------
__global__ void k_scanB() {
    __shared__ int ws[16];
    int t = threadIdx.x;
    int v = (t < NB) ? g_bsum[t] : 0;
    int lane = t & 31, wid = t >> 5;
    int x = v;
    #pragma unroll
    for (int o = 1; o < 32; o <<= 1) {
        int y = __shfl_up_sync(0xffffffffu, x, o);
        if (lane >= o) x += y;
    }
    if (lane == 31) ws[wid] = x;
    __syncthreads();
    if (wid == 0) {
        int s = (lane < 16) ? ws[lane] : 0;
        #pragma unroll
        for (int o = 1; o < 32; o <<= 1) {
            int y = __shfl_up_sync(0xffffffffu, s, o);
            if (lane >= o) s += y;
        }
        if (lane < 16) ws[lane] = s;
    }
    __syncthreads();
    int excl = x - v + (wid > 0 ? ws[wid - 1] : 0);
    if (t < NB) g_bsum[t] = excl;
    if (t == 0) g_rowptr[NT] = ws[15];   // = NE
}

// -------- fused: scanC (rowptr fix-up) + init (y0 = dinv*x fp16), 32B/thread ----
__global__ void k_fixinit(const float4* __restrict__ uw, const float4* __restrict__ iw) {
    int i = blockIdx.x * blockDim.x + threadIdx.x;   // uint4 index into g_a: NT*8 total
    if (i < NT) g_rowptr[i] += g_bsum[i >> 10];
    const int NTQ = NT * 8;
    if (i >= NTQ) return;
    int r = i >> 3;                                  // node
    float di = g_dinv[r];
    int fo = i * 2;                                  // float4 index into x
    const float4* xs = (r < NU) ? uw + fo : iw + (fo - NU * 16);
    float4 v0 = xs[0];
    float4 v1 = xs[1];
    __half2 h0 = __floats2half2_rn(di * v0.x, di * v0.y);
    __half2 h1 = __floats2half2_rn(di * v0.z, di * v0.w);
    __half2 h2 = __floats2half2_rn(di * v1.x, di * v1.y);
    __half2 h3 = __floats2half2_rn(di * v1.z, di * v1.w);
    uint4 raw;
    raw.x = *(const unsigned*)&h0;
    raw.y = *(const unsigned*)&h1;
    raw.z = *(const unsigned*)&h2;
    raw.w = *(const unsigned*)&h3;
    ((uint4*)g_a)[i] = raw;
}

// -------- build: scatter edges into CSR, 2 edges per thread --------
__global__ void k_scatter(const int2* __restrict__ src2, const int2* __restrict__ dst2) {
    int i = blockIdx.x * blockDim.x + threadIdx.x;
    if (i < NE / 2) {
        int2 s = src2[i];
        int2 d = dst2[i];
        int p0 = atomicAdd(&g_pos[s.x], 1);
        g_col[g_rowptr[s.x] + p0] = d.x;
        int p1 = atomicAdd(&g_pos[s.y], 1);
        g_col[g_rowptr[s.y] + p1] = d.y;
    }
}

// -------- SpMM: 4 rows per warp; 8 lanes per row, lane owns 8 dims (uint4) --------
// Col loads software-pipelined. LAST=1: fused epilogue, x reconstructed from y0.
template<int S, int DBUF, int LAST>
__global__ void __launch_bounds__(256) k_spmm(float4* __restrict__ out) {
    int w = (blockIdx.x * 256 + threadIdx.x) >> 5;   // warp id: 0 .. NT/4-1
    if (w >= NT / 4) return;
    int lane  = threadIdx.x & 31;
    int lane8 = lane & 7;
    int seg   = lane >> 3;                           // 0..3
    int r = w * 4 + seg;                             // this segment's row

    const uint4* __restrict__ y = (const uint4*)buf(S);

    int beg = g_rowptr[r];
    int n   = g_rowptr[r + 1] - beg;
    // warp-wide max degree over the 4 segments
    int nMax = n;
    nMax = max(nMax, __shfl_xor_sync(0xffffffffu, nMax, 8));
    nMax = max(nMax, __shfl_xor_sync(0xffffffffu, nMax, 16));

    float a0 = 0.f, a1 = 0.f, a2 = 0.f, a3 = 0.f;
    float a4 = 0.f, a5 = 0.f, a6 = 0.f, a7 = 0.f;

    int myc = (lane8 < n) ? g_col[beg + lane8] : -1;          // prefetch iter 0
    for (int base = 0; base < nMax; base += 8) {
        int ne = base + 8 + lane8;
        int nextc = (base + 8 < nMax && ne < n) ? g_col[beg + ne] : -1;  // prefetch next
        #pragma unroll
        for (int k = 0; k < 8; k++) {
            int c = __shfl_sync(0xffffffffu, myc, k, 8);   // within 8-lane segment
            if (c >= 0) {
                uint4 raw = y[c * 8 + lane8];
                float2 f0 = __half22float2(*(const __half2*)&raw.x);
                float2 f1 = __half22float2(*(const __half2*)&raw.y);
                float2 f2 = __half22float2(*(const __half2*)&raw.z);
                float2 f3 = __half22float2(*(const __half2*)&raw.w);
                a0 += f0.x; a1 += f0.y; a2 += f1.x; a3 += f1.y;
                a4 += f2.x; a5 += f2.y; a6 += f3.x; a7 += f3.y;
            }
        }
        myc = nextc;
    }

    float di = g_dinv[r];
    int o = r * 8 + lane8;                           // uint4 index within y-layout
    if (!LAST) {
        float f = di * di;
        __half2 h0 = __floats2half2_rn(f * a0, f * a1);
        __half2 h1 = __floats2half2_rn(f * a2, f * a3);
        __half2 h2 = __floats2half2_rn(f * a4, f * a5);
        __half2 h3 = __floats2half2_rn(f * a6, f * a7);
        uint4 raw;
        raw.x = *(const unsigned*)&h0;
        raw.y = *(const unsigned*)&h1;
        raw.z = *(const unsigned*)&h2;
        raw.w = *(const unsigned*)&h3;
        ((uint4*)buf(DBUF))[o] = raw;
    } else {
        // h3 = di*s; x = inv*y0; out = 0.25*(x + inv*(y1+y2) + h3)
        //          = 0.25*(inv*(y0+y1+y2) + di*s)
        float inv = __frcp_rn(di);                   // = sqrt(deg + 1e-8)
        uint4 ra = ((const uint4*)g_a)[o];
        uint4 rb = ((const uint4*)g_b)[o];
        uint4 rc = ((const uint4*)g_c)[o];
        float2 A0 = __half22float2(*(const __half2*)&ra.x);
        float2 A1 = __half22float2(*(const __half2*)&ra.y);
        float2 A2 = __half22float2(*(const __half2*)&ra.z);
        float2 A3 = __half22float2(*(const __half2*)&ra.w);
        float2 B0 = __half22float2(*(const __half2*)&rb.x);
        float2 B1 = __half22float2(*(const __half2*)&rb.y);
        float2 B2 = __half22float2(*(const __half2*)&rb.z);
        float2 B3 = __half22float2(*(const __half2*)&rb.w);
        float2 C0 = __half22float2(*(const __half2*)&rc.x);
        float2 C1 = __half22float2(*(const __half2*)&rc.y);
        float2 C2 = __half22float2(*(const __half2*)&rc.z);
        float2 C3 = __half22float2(*(const __half2*)&rc.w);
        int fo = r * 16 + lane8 * 2;                 // float4 index (row = 16 float4)
        out[fo] = make_float4(
            0.25f * (inv * (A0.x + B0.x + C0.x) + di * a0),
            0.25f * (inv * (A0.y + B0.y + C0.y) + di * a1),
            0.25f * (inv * (A1.x + B1.x + C1.x) + di * a2),
            0.25f * (inv * (A1.y + B1.y + C1.y) + di * a3));
        out[fo + 1] = make_float4(
            0.25f * (inv * (A2.x + B2.x + C2.x) + di * a4),
            0.25f * (inv * (A2.y + B2.y + C2.y) + di * a5),
            0.25f * (inv * (A3.x + B3.x + C3.x) + di * a6),
            0.25f * (inv * (A3.y + B3.y + C3.y) + di * a7));
    }
}

extern "C" void kernel_launch(void* const* d_in, const int* in_sizes, int n_in,
                              void* d_out, int out_size) {
    const float* uw  = (const float*)d_in[0];
    const float* iw  = (const float*)d_in[1];
    const int*   src = (const int*)d_in[2];
    const int*   dst = (const int*)d_in[3];
    float* out = (float*)d_out;

    // zero deg + pos via memset nodes
    void *p_deg = nullptr, *p_pos = nullptr;
    cudaGetSymbolAddress(&p_deg, g_deg);
    cudaGetSymbolAddress(&p_pos, g_pos);
    cudaMemsetAsync(p_deg, 0, NT * sizeof(int));
    cudaMemsetAsync(p_pos, 0, NT * sizeof(int));

    // CSR build + init
    k_hist<<<(NE / 4 + 255) / 256, 256>>>((const int4*)src);
    k_scanA<<<NB, 1024>>>();
    k_scanB<<<1, 512>>>();
    k_fixinit<<<(NT * 8 + 255) / 256, 256>>>((const float4*)uw, (const float4*)iw);
    k_scatter<<<(NE / 2 + 255) / 256, 256>>>((const int2*)src, (const int2*)dst);

    // 3 propagation layers; 4 rows per warp
    int nblk = (NT / 4 * 32 + 255) / 256;
    k_spmm<0, 1, 0><<<nblk, 256>>>((float4*)out);
    k_spmm<1, 2, 0><<<nblk, 256>>>((float4*)out);
    k_spmm<2, 0, 1><<<nblk, 256>>>((float4*)out);
}